// round 2
// baseline (speedup 1.0000x reference)
#include <cuda_runtime.h>

// Conv2d 3x3 s2 p1: x[16,256,64,64] * w[256,256,3,3] + bias, output written in
// stride-permuted order. Implicit GEMM: M=16384 (n,p-permuted), N=256 (cout),
// K=2304 (cin*9). BK=9 => one cin per K-step; gather coords precomputed.

#define CIN   256
#define HH    64
#define WW    64
#define COUT  256
#define PP    1024           // 32*32 spatial positions per image
#define BM    128
#define BN    128
#define BK    9

__global__ __launch_bounds__(256, 2)
void conv_sgemm_kernel(const float* __restrict__ x,
                       const float* __restrict__ wgt,
                       const float* __restrict__ bias,
                       float* __restrict__ out)
{
    __shared__ float As[BK][BM];
    __shared__ float Bs[BK][BN];

    const int tid = threadIdx.x;      // 0..255
    const int tx  = tid & 15;         // output-channel group
    const int ty  = tid >> 4;         // m group

    const int mb = blockIdx.x;        // 0..127  (M blocks)
    const int cb = blockIdx.y;        // 0..1    (N blocks)

    // ---------------- A-tile load precompute (fixed across cin loop) --------
    // A tile: 128 m x 9 k = 1152 elems; thread owns m_local = tid&127 and
    // k in {khalf, khalf+2, ..., khalf+8} (khalf = tid>>7). Max 5 slots.
    const int mloc  = tid & 127;
    const int khalf = tid >> 7;

    {
        // nothing
    }
    const int m  = mb * BM + mloc;
    const int n  = m >> 10;           // batch
    const int p  = m & 1023;          // permuted spatial index
    const int si = (p >> 9) & 1;
    const int sj = (p >> 8) & 1;
    const int pi = (p >> 4) & 15;
    const int pj = p & 15;
    const int ybase = 2 * (2 * pi + si) - 1;   // input row for kh=0
    const int xbase = 2 * (2 * pj + sj) - 1;   // input col for kw=0

    int  aoff[5];
    bool avld[5];
    int  boff[5];
    const int cloc   = tid & 127;
    const int cout_l = cb * BN + cloc;
#pragma unroll
    for (int s = 0; s < 5; s++) {
        const int k  = khalf + 2 * s;        // 0..9
        const int kh = k / 3;
        const int kw = k - 3 * kh;
        const int y  = ybase + kh;
        const int xx = xbase + kw;
        avld[s] = (k < 9) && (y >= 0) && (y < HH) && (xx >= 0) && (xx < WW);
        aoff[s] = n * (CIN * HH * WW) + y * WW + xx;
        boff[s] = cout_l * (CIN * 9) + k;    // weight[cout][cin][kh][kw]
    }

    float acc[8][8];
#pragma unroll
    for (int i = 0; i < 8; i++)
#pragma unroll
        for (int j = 0; j < 8; j++) acc[i][j] = 0.0f;

    // ---------------- main loop over input channels -------------------------
    for (int cin = 0; cin < CIN; ++cin) {
        const int xch = cin * (HH * WW);
        const int wch = cin * 9;
#pragma unroll
        for (int s = 0; s < 5; s++) {
            const int k = khalf + 2 * s;
            if (k < 9) {
                float va = avld[s] ? __ldg(&x[aoff[s] + xch]) : 0.0f;
                As[k][mloc] = va;
                Bs[k][cloc] = __ldg(&wgt[boff[s] + wch]);
            }
        }
        __syncthreads();

#pragma unroll
        for (int kk = 0; kk < BK; ++kk) {
            const float4 a0 = *(const float4*)&As[kk][ty * 8];
            const float4 a1 = *(const float4*)&As[kk][ty * 8 + 4];
            const float4 b0 = *(const float4*)&Bs[kk][tx * 8];
            const float4 b1 = *(const float4*)&Bs[kk][tx * 8 + 4];
            const float a[8] = {a0.x, a0.y, a0.z, a0.w, a1.x, a1.y, a1.z, a1.w};
            const float b[8] = {b0.x, b0.y, b0.z, b0.w, b1.x, b1.y, b1.z, b1.w};
#pragma unroll
            for (int i = 0; i < 8; i++)
#pragma unroll
                for (int j = 0; j < 8; j++)
                    acc[i][j] = fmaf(a[i], b[j], acc[i][j]);
        }
        __syncthreads();
    }

    // ---------------- epilogue: bias + permuted store -----------------------
    // Thread's 8 m's are consecutive p within one batch -> float4 stores.
    const int cout0 = cb * BN + tx * 8;
    const int m0    = mb * BM + ty * 8;
    const int nn    = m0 >> 10;
    const int p0    = m0 & 1023;

#pragma unroll
    for (int j = 0; j < 8; j++) {
        const float bv = __ldg(&bias[cout0 + j]);
        float4 v0, v1;
        v0.x = acc[0][j] + bv; v0.y = acc[1][j] + bv;
        v0.z = acc[2][j] + bv; v0.w = acc[3][j] + bv;
        v1.x = acc[4][j] + bv; v1.y = acc[5][j] + bv;
        v1.z = acc[6][j] + bv; v1.w = acc[7][j] + bv;
        float* dst = out + ((size_t)(nn * COUT + cout0 + j)) * PP + p0;
        *(float4*)(dst)     = v0;
        *(float4*)(dst + 4) = v1;
    }
}

extern "C" void kernel_launch(void* const* d_in, const int* in_sizes, int n_in,
                              void* d_out, int out_size)
{
    (void)in_sizes; (void)n_in; (void)out_size;
    const float* x    = (const float*)d_in[0];
    const float* wgt  = (const float*)d_in[1];
    const float* bias = (const float*)d_in[2];
    float* out        = (float*)d_out;

    dim3 grid(128, 2);   // M blocks x N blocks
    dim3 block(256);
    conv_sgemm_kernel<<<grid, block>>>(x, wgt, bias, out);
}

// round 4
// speedup vs baseline: 2.9268x; 2.9268x over previous
#include <cuda_runtime.h>
#include <cuda_bf16.h>
#include <cstdint>

// Conv2d 3x3 s2 p1 as implicit GEMM with mma.sync (bf16 hi/lo split, fp32 acc).
// Compiles under plain sm_103 PTX target (no tcgen05 / no 'a' features).
// x[16,256,64,64] fp32, w[256,256,3,3] fp32, bias[256] -> out fp32, permuted.
// M = 16384 (m = n*1024 + permuted p), N = 256, K = 2304 = 72 chunks of 32.

#define CIN    256
#define COUT   256
#define HW     64
#define PP     1024
#define KTOT   2304
#define NCHUNK 72

#define SWZ(o) ((o) ^ (((o) >> 3) & 0x70))

// preconverted weights (hi/lo bf16), K-major [cout][k]
__device__ __align__(16) __nv_bfloat16 g_whi[COUT * KTOT];
__device__ __align__(16) __nv_bfloat16 g_wlo[COUT * KTOT];

__global__ void wconv_kernel(const float* __restrict__ w) {
    int i = blockIdx.x * blockDim.x + threadIdx.x;
    if (i < COUT * KTOT) {
        float v = w[i];
        __nv_bfloat16 h = __float2bfloat16(v);
        g_whi[i] = h;
        g_wlo[i] = __float2bfloat16(v - __bfloat162float(h));
    }
}

__device__ __forceinline__ uint32_t smem_u32_of(const void* p) {
    uint32_t a;
    asm("{ .reg .u64 t; cvta.to.shared.u64 t, %1; cvt.u32.u64 %0, t; }" : "=r"(a) : "l"(p));
    return a;
}

#define LDMATRIX_X4(r0, r1, r2, r3, addr)                                    \
    asm volatile("ldmatrix.sync.aligned.m8n8.x4.shared.b16 {%0,%1,%2,%3}, [%4];" \
                 : "=r"(r0), "=r"(r1), "=r"(r2), "=r"(r3) : "r"(addr))

#define MMA16816(d, a, b0, b1)                                               \
    asm volatile("mma.sync.aligned.m16n8k16.row.col.f32.bf16.bf16.f32 "      \
                 "{%0,%1,%2,%3},{%4,%5,%6,%7},{%8,%9},{%0,%1,%2,%3};"        \
                 : "+f"((d)[0]), "+f"((d)[1]), "+f"((d)[2]), "+f"((d)[3])    \
                 : "r"((a)[0]), "r"((a)[1]), "r"((a)[2]), "r"((a)[3]),       \
                   "r"(b0), "r"(b1))

#define CP_ASYNC16(dst, src) \
    asm volatile("cp.async.cg.shared.global [%0], [%1], 16;" :: "r"(dst), "l"(src))

// smem: A stages [0, 32KB), B stages [32KB, 64KB); each stage 16KB:
// row (0..127) * 128B = [hi 64B | lo 64B] of 32 k-elems, SWZ-swizzled.
#define STAGE 16384
#define SMEM_TOTAL 65536

__global__ __launch_bounds__(256, 1)
void conv_mma_kernel(const float* __restrict__ x,
                     const float* __restrict__ bias,
                     float* __restrict__ out)
{
    extern __shared__ char smem[];
    const uint32_t smem_u = smem_u32_of(smem);
    const uint32_t aBase = smem_u;
    const uint32_t bBase = smem_u + 2 * STAGE;

    const int tid = threadIdx.x;
    const int lid = tid & 31;
    const int wid = tid >> 5;
    const int nb  = blockIdx.x;     // 0..1
    const int mb  = blockIdx.y;     // 0..127

    // ---- A gather geometry (permutation folded into m) ----
    const int row  = tid & 127;
    const int half = tid >> 7;
    const int mg   = mb * 128 + row;
    const int nimg = mg >> 10;
    const int p    = mg & 1023;
    const int si = (p >> 9) & 1, sj = (p >> 8) & 1;
    const int pi = (p >> 4) & 15, pj = p & 15;
    const int ybase = 4 * pi + 2 * si - 1;
    const int xbase = 4 * pj + 2 * sj - 1;
    const float* xb = x + (size_t)nimg * CIN * HW * HW;

    // ---- B cp.async mapping: 4 x 16B per thread per chunk ----
    const __nv_bfloat16* bsrc[4];
    uint32_t bdst[4];
    {
#pragma unroll
        for (int i = 0; i < 4; i++) {
            const int q    = i * 256 + tid;     // 0..1023
            const int brow = q >> 3;
            const int unit = q & 7;
            const int term = unit >> 2;         // 0=hi,1=lo
            const int k16  = unit & 3;
            const __nv_bfloat16* base = term ? g_wlo : g_whi;
            bsrc[i] = base + (size_t)(nb * 128 + brow) * KTOT + k16 * 8;
            bdst[i] = SWZ((uint32_t)(brow * 128 + unit * 16));
        }
    }

    float acc[4][4][4];
#pragma unroll
    for (int a = 0; a < 4; a++)
#pragma unroll
        for (int b = 0; b < 4; b++)
#pragma unroll
            for (int c = 0; c < 4; c++) acc[a][b][c] = 0.0f;

    float v[16];

    // ---- gather A for chunk c into v ----
    auto gatherA = [&](int c) {
#pragma unroll
        for (int j = 0; j < 16; j++) {
            const int k   = c * 32 + half * 16 + j;
            const int cin = (k * 7282) >> 16;       // k/9 for k<2304
            const int tap = k - cin * 9;
            const int kh  = (tap * 11) >> 5;        // tap/3
            const int kw  = tap - kh * 3;
            const int y   = ybase + kh;
            const int xx  = xbase + kw;
            const bool ok = ((unsigned)y < HW) & ((unsigned)xx < HW);
            const float* a = xb + (cin << 12) + (y << 6) + xx;
            v[j] = ok ? __ldg(a) : 0.0f;
        }
    };

    auto stsA = [&](int c) {
        char* abuf = smem + (c & 1) * STAGE;
#pragma unroll
        for (int j = 0; j < 16; j += 2) {
            __nv_bfloat16 h0 = __float2bfloat16(v[j]);
            __nv_bfloat16 h1 = __float2bfloat16(v[j + 1]);
            __nv_bfloat16 l0 = __float2bfloat16(v[j] - __bfloat162float(h0));
            __nv_bfloat16 l1 = __float2bfloat16(v[j + 1] - __bfloat162float(h1));
            const uint32_t hp = (uint32_t)__bfloat16_as_ushort(h0) |
                                ((uint32_t)__bfloat16_as_ushort(h1) << 16);
            const uint32_t lp = (uint32_t)__bfloat16_as_ushort(l0) |
                                ((uint32_t)__bfloat16_as_ushort(l1) << 16);
            const uint32_t byte = (uint32_t)(row * 128 + half * 32 + j * 2);
            *(uint32_t*)(abuf + SWZ(byte))      = hp;
            *(uint32_t*)(abuf + SWZ(byte + 64)) = lp;
        }
    };

    auto issueB = [&](int c) {
        const uint32_t bb = bBase + (c & 1) * STAGE;
#pragma unroll
        for (int i = 0; i < 4; i++)
            CP_ASYNC16(bb + bdst[i], (const void*)(bsrc[i] + c * 32));
        asm volatile("cp.async.commit_group;");
    };

    const int wm = wid >> 2;   // 0..1
    const int wn = wid & 3;    // 0..3

    // ---- prologue ----
    gatherA(0);
    issueB(0);

    for (int c = 0; c < NCHUNK; ++c) {
        stsA(c);
        if (c < NCHUNK - 1) gatherA(c + 1);
        asm volatile("cp.async.wait_group 0;");
        __syncthreads();
        if (c < NCHUNK - 1) issueB(c + 1);

        const uint32_t ab = aBase + (c & 1) * STAGE;
        const uint32_t bb = bBase + (c & 1) * STAGE;

#pragma unroll
        for (int kb = 0; kb < 2; kb++) {
            uint32_t AH[4][4], AL[4][4], BH[2][4], BL[2][4];
#pragma unroll
            for (int mt = 0; mt < 4; mt++) {
                const int mrow = wm * 64 + mt * 16 + ((lid >> 3) & 1) * 8 + (lid & 7);
                const int kbyH = kb * 32 + (lid >> 4) * 16;
                LDMATRIX_X4(AH[mt][0], AH[mt][1], AH[mt][2], AH[mt][3],
                            ab + SWZ((uint32_t)(mrow * 128 + kbyH)));
                LDMATRIX_X4(AL[mt][0], AL[mt][1], AL[mt][2], AL[mt][3],
                            ab + SWZ((uint32_t)(mrow * 128 + 64 + kbyH)));
            }
#pragma unroll
            for (int np = 0; np < 2; np++) {
                const int nrow = wn * 32 + np * 16 + (lid >> 4) * 8 + (lid & 7);
                const int kbyH = kb * 32 + ((lid >> 3) & 1) * 16;
                LDMATRIX_X4(BH[np][0], BH[np][1], BH[np][2], BH[np][3],
                            bb + SWZ((uint32_t)(nrow * 128 + kbyH)));
                LDMATRIX_X4(BL[np][0], BL[np][1], BL[np][2], BL[np][3],
                            bb + SWZ((uint32_t)(nrow * 128 + 64 + kbyH)));
            }
#pragma unroll
            for (int mt = 0; mt < 4; mt++) {
#pragma unroll
                for (int nt = 0; nt < 4; nt++) {
                    const int np = nt >> 1, sb = (nt & 1) * 2;
                    MMA16816(acc[mt][nt], AH[mt], BH[np][sb], BH[np][sb + 1]);
                    MMA16816(acc[mt][nt], AH[mt], BL[np][sb], BL[np][sb + 1]);
                    MMA16816(acc[mt][nt], AL[mt], BH[np][sb], BH[np][sb + 1]);
                }
            }
        }
    }

    // ---- epilogue: bias + permuted store ----
#pragma unroll
    for (int mt = 0; mt < 4; mt++) {
#pragma unroll
        for (int nt = 0; nt < 4; nt++) {
            const int m0 = mb * 128 + wm * 64 + mt * 16 + (lid >> 2);
            const int c0 = nb * 128 + wn * 32 + nt * 8 + (lid & 3) * 2;
            const int ni = m0 >> 10;
            const int p0 = m0 & 1023;
            const float2 bv = *(const float2*)&bias[c0];
            float* o0 = out + ((size_t)(ni * COUT + c0)) * PP;
            float* o1 = o0 + PP;
            o0[p0]     = acc[mt][nt][0] + bv.x;
            o1[p0]     = acc[mt][nt][1] + bv.y;
            o0[p0 + 8] = acc[mt][nt][2] + bv.x;
            o1[p0 + 8] = acc[mt][nt][3] + bv.y;
        }
    }
}

extern "C" void kernel_launch(void* const* d_in, const int* in_sizes, int n_in,
                              void* d_out, int out_size)
{
    (void)in_sizes; (void)n_in; (void)out_size;
    const float* x    = (const float*)d_in[0];
    const float* wgt  = (const float*)d_in[1];
    const float* bias = (const float*)d_in[2];
    float* out        = (float*)d_out;

    wconv_kernel<<<(COUT * KTOT + 511) / 512, 512>>>(wgt);

    cudaFuncSetAttribute(conv_mma_kernel,
                         cudaFuncAttributeMaxDynamicSharedMemorySize, SMEM_TOTAL);
    dim3 grid(2, 128);
    conv_mma_kernel<<<grid, 256, SMEM_TOTAL>>>(x, bias, out);
}

// round 6
// speedup vs baseline: 2.9379x; 1.0038x over previous
#include <cuda_runtime.h>
#include <cuda_bf16.h>
#include <cstdint>

// Conv2d 3x3 s2 p1 as implicit GEMM with mma.sync (bf16 hi/lo split, fp32 acc).
// R4: __launch_bounds__(256,2) for 2 CTAs/SM (single wave of 256 CTAs),
// A-fragments loaded per-mt to cut register pressure (194 -> <=128).
// x[16,256,64,64] fp32, w[256,256,3,3] fp32, bias[256] -> out fp32, permuted.
// M = 16384 (m = n*1024 + permuted p), N = 256, K = 2304 = 72 chunks of 32.

#define CIN    256
#define COUT   256
#define HW     64
#define PP     1024
#define KTOT   2304
#define NCHUNK 72

#define SWZ(o) ((o) ^ (((o) >> 3) & 0x70))

// preconverted weights (hi/lo bf16), K-major [cout][k]
__device__ __align__(16) __nv_bfloat16 g_whi[COUT * KTOT];
__device__ __align__(16) __nv_bfloat16 g_wlo[COUT * KTOT];

__global__ void wconv_kernel(const float* __restrict__ w) {
    int i = blockIdx.x * blockDim.x + threadIdx.x;
    if (i < COUT * KTOT) {
        float v = w[i];
        __nv_bfloat16 h = __float2bfloat16(v);
        g_whi[i] = h;
        g_wlo[i] = __float2bfloat16(v - __bfloat162float(h));
    }
}

__device__ __forceinline__ uint32_t smem_u32_of(const void* p) {
    uint32_t a;
    asm("{ .reg .u64 t; cvta.to.shared.u64 t, %1; cvt.u32.u64 %0, t; }" : "=r"(a) : "l"(p));
    return a;
}

#define LDMATRIX_X4(r0, r1, r2, r3, addr)                                    \
    asm volatile("ldmatrix.sync.aligned.m8n8.x4.shared.b16 {%0,%1,%2,%3}, [%4];" \
                 : "=r"(r0), "=r"(r1), "=r"(r2), "=r"(r3) : "r"(addr))

#define MMA16816(d, a, b0, b1)                                               \
    asm volatile("mma.sync.aligned.m16n8k16.row.col.f32.bf16.bf16.f32 "      \
                 "{%0,%1,%2,%3},{%4,%5,%6,%7},{%8,%9},{%0,%1,%2,%3};"        \
                 : "+f"((d)[0]), "+f"((d)[1]), "+f"((d)[2]), "+f"((d)[3])    \
                 : "r"((a)[0]), "r"((a)[1]), "r"((a)[2]), "r"((a)[3]),       \
                   "r"(b0), "r"(b1))

#define CP_ASYNC16(dst, src) \
    asm volatile("cp.async.cg.shared.global [%0], [%1], 16;" :: "r"(dst), "l"(src))

// smem: A stages [0, 32KB), B stages [32KB, 64KB); each stage 16KB:
// row (0..127) * 128B = [hi 64B | lo 64B] of 32 k-elems, SWZ-swizzled.
#define STAGE 16384
#define SMEM_TOTAL 65536

__global__ __launch_bounds__(256, 2)
void conv_mma_kernel(const float* __restrict__ x,
                     const float* __restrict__ bias,
                     float* __restrict__ out)
{
    extern __shared__ char smem[];
    const uint32_t smem_u = smem_u32_of(smem);
    const uint32_t aBase = smem_u;
    const uint32_t bBase = smem_u + 2 * STAGE;

    const int tid = threadIdx.x;
    const int lid = tid & 31;
    const int wid = tid >> 5;
    const int nb  = blockIdx.x;     // 0..1
    const int mb  = blockIdx.y;     // 0..127

    // ---- A gather geometry (permutation folded into m) ----
    const int row  = tid & 127;
    const int half = tid >> 7;
    const int mg   = mb * 128 + row;
    const int nimg = mg >> 10;
    const int p    = mg & 1023;
    const int si = (p >> 9) & 1, sj = (p >> 8) & 1;
    const int pi = (p >> 4) & 15, pj = p & 15;
    const int ybase = 4 * pi + 2 * si - 1;
    const int xbase = 4 * pj + 2 * sj - 1;
    const float* xb = x + (size_t)nimg * CIN * HW * HW;

    // ---- B cp.async mapping: 4 x 16B per thread per chunk ----
    const __nv_bfloat16* bsrc[4];
    uint32_t bdst[4];
    {
#pragma unroll
        for (int i = 0; i < 4; i++) {
            const int q    = i * 256 + tid;     // 0..1023
            const int brow = q >> 3;
            const int unit = q & 7;
            const int term = unit >> 2;         // 0=hi,1=lo
            const int k16  = unit & 3;
            const __nv_bfloat16* base = term ? g_wlo : g_whi;
            bsrc[i] = base + (size_t)(nb * 128 + brow) * KTOT + k16 * 8;
            bdst[i] = SWZ((uint32_t)(brow * 128 + unit * 16));
        }
    }

    float acc[4][4][4];
#pragma unroll
    for (int a = 0; a < 4; a++)
#pragma unroll
        for (int b = 0; b < 4; b++)
#pragma unroll
            for (int c = 0; c < 4; c++) acc[a][b][c] = 0.0f;

    float v[16];

    // ---- gather A for chunk c into v ----
    auto gatherA = [&](int c) {
#pragma unroll
        for (int j = 0; j < 16; j++) {
            const int k   = c * 32 + half * 16 + j;
            const int cin = (k * 7282) >> 16;       // k/9 for k<2304
            const int tap = k - cin * 9;
            const int kh  = (tap * 11) >> 5;        // tap/3
            const int kw  = tap - kh * 3;
            const int y   = ybase + kh;
            const int xx  = xbase + kw;
            const bool ok = ((unsigned)y < HW) & ((unsigned)xx < HW);
            const float* a = xb + (cin << 12) + (y << 6) + xx;
            v[j] = ok ? __ldg(a) : 0.0f;
        }
    };

    auto stsA = [&](int c) {
        char* abuf = smem + (c & 1) * STAGE;
#pragma unroll
        for (int j = 0; j < 16; j += 2) {
            __nv_bfloat16 h0 = __float2bfloat16(v[j]);
            __nv_bfloat16 h1 = __float2bfloat16(v[j + 1]);
            __nv_bfloat16 l0 = __float2bfloat16(v[j] - __bfloat162float(h0));
            __nv_bfloat16 l1 = __float2bfloat16(v[j + 1] - __bfloat162float(h1));
            const uint32_t hp = (uint32_t)__bfloat16_as_ushort(h0) |
                                ((uint32_t)__bfloat16_as_ushort(h1) << 16);
            const uint32_t lp = (uint32_t)__bfloat16_as_ushort(l0) |
                                ((uint32_t)__bfloat16_as_ushort(l1) << 16);
            const uint32_t byte = (uint32_t)(row * 128 + half * 32 + j * 2);
            *(uint32_t*)(abuf + SWZ(byte))      = hp;
            *(uint32_t*)(abuf + SWZ(byte + 64)) = lp;
        }
    };

    auto issueB = [&](int c) {
        const uint32_t bb = bBase + (c & 1) * STAGE;
#pragma unroll
        for (int i = 0; i < 4; i++)
            CP_ASYNC16(bb + bdst[i], (const void*)(bsrc[i] + c * 32));
        asm volatile("cp.async.commit_group;");
    };

    const int wm = wid >> 2;   // 0..1
    const int wn = wid & 3;    // 0..3

    // ---- prologue ----
    gatherA(0);
    issueB(0);

    for (int c = 0; c < NCHUNK; ++c) {
        stsA(c);
        if (c < NCHUNK - 1) gatherA(c + 1);
        asm volatile("cp.async.wait_group 0;");
        __syncthreads();
        if (c < NCHUNK - 1) issueB(c + 1);

        const uint32_t ab = aBase + (c & 1) * STAGE;
        const uint32_t bb = bBase + (c & 1) * STAGE;

#pragma unroll
        for (int kb = 0; kb < 2; kb++) {
            // B fragments for this kb (16 regs live)
            uint32_t BH[2][4], BL[2][4];
#pragma unroll
            for (int np = 0; np < 2; np++) {
                const int nrow = wn * 32 + np * 16 + (lid >> 4) * 8 + (lid & 7);
                const int kbyH = kb * 32 + ((lid >> 3) & 1) * 16;
                LDMATRIX_X4(BH[np][0], BH[np][1], BH[np][2], BH[np][3],
                            bb + SWZ((uint32_t)(nrow * 128 + kbyH)));
                LDMATRIX_X4(BL[np][0], BL[np][1], BL[np][2], BL[np][3],
                            bb + SWZ((uint32_t)(nrow * 128 + 64 + kbyH)));
            }
            // A fragments loaded per-mt (8 regs live at a time)
#pragma unroll
            for (int mt = 0; mt < 4; mt++) {
                uint32_t AH[4], AL[4];
                const int mrow = wm * 64 + mt * 16 + ((lid >> 3) & 1) * 8 + (lid & 7);
                const int kbyH = kb * 32 + (lid >> 4) * 16;
                LDMATRIX_X4(AH[0], AH[1], AH[2], AH[3],
                            ab + SWZ((uint32_t)(mrow * 128 + kbyH)));
                LDMATRIX_X4(AL[0], AL[1], AL[2], AL[3],
                            ab + SWZ((uint32_t)(mrow * 128 + 64 + kbyH)));
#pragma unroll
                for (int nt = 0; nt < 4; nt++) {
                    const int np = nt >> 1, sb = (nt & 1) * 2;
                    MMA16816(acc[mt][nt], AH, BH[np][sb], BH[np][sb + 1]);
                    MMA16816(acc[mt][nt], AH, BL[np][sb], BL[np][sb + 1]);
                    MMA16816(acc[mt][nt], AL, BH[np][sb], BH[np][sb + 1]);
                }
            }
        }
    }

    // ---- epilogue: bias + permuted store ----
#pragma unroll
    for (int mt = 0; mt < 4; mt++) {
#pragma unroll
        for (int nt = 0; nt < 4; nt++) {
            const int m0 = mb * 128 + wm * 64 + mt * 16 + (lid >> 2);
            const int c0 = nb * 128 + wn * 32 + nt * 8 + (lid & 3) * 2;
            const int ni = m0 >> 10;
            const int p0 = m0 & 1023;
            const float2 bv = *(const float2*)&bias[c0];
            float* o0 = out + ((size_t)(ni * COUT + c0)) * PP;
            float* o1 = o0 + PP;
            o0[p0]     = acc[mt][nt][0] + bv.x;
            o1[p0]     = acc[mt][nt][1] + bv.y;
            o0[p0 + 8] = acc[mt][nt][2] + bv.x;
            o1[p0 + 8] = acc[mt][nt][3] + bv.y;
        }
    }
}

extern "C" void kernel_launch(void* const* d_in, const int* in_sizes, int n_in,
                              void* d_out, int out_size)
{
    (void)in_sizes; (void)n_in; (void)out_size;
    const float* x    = (const float*)d_in[0];
    const float* wgt  = (const float*)d_in[1];
    const float* bias = (const float*)d_in[2];
    float* out        = (float*)d_out;

    wconv_kernel<<<(COUT * KTOT + 511) / 512, 512>>>(wgt);

    cudaFuncSetAttribute(conv_mma_kernel,
                         cudaFuncAttributeMaxDynamicSharedMemorySize, SMEM_TOTAL);
    dim3 grid(2, 128);
    conv_mma_kernel<<<grid, 256, SMEM_TOTAL>>>(x, bias, out);
}

// round 7
// speedup vs baseline: 3.8007x; 1.2937x over previous
#include <cuda_runtime.h>
#include <cuda_bf16.h>
#include <cstdint>

// Conv2d 3x3 s2 p1 as implicit GEMM with mma.sync (bf16 hi/lo split, fp32 acc).
// R6: raster m-mapping (coalesced gather), BM=64 x BN=256 (A gathered once),
// permutation folded into epilogue store index only.
// x[16,256,64,64] fp32, w[256,256,3,3] fp32, bias[256] -> out fp32, permuted.
// M = 16384, N = 256, K = 2304 = 72 chunks of 32.

#define CIN    256
#define COUT   256
#define HW     64
#define PP     1024
#define KTOT   2304
#define NCHUNK 72

#define SWZ(o) ((o) ^ (((o) >> 3) & 0x70))

// preconverted weights (hi/lo bf16), K-major [cout][k]
__device__ __align__(16) __nv_bfloat16 g_whi[COUT * KTOT];
__device__ __align__(16) __nv_bfloat16 g_wlo[COUT * KTOT];

__global__ void wconv_kernel(const float* __restrict__ w) {
    int i = blockIdx.x * blockDim.x + threadIdx.x;
    if (i < COUT * KTOT) {
        float v = w[i];
        __nv_bfloat16 h = __float2bfloat16(v);
        g_whi[i] = h;
        g_wlo[i] = __float2bfloat16(v - __bfloat162float(h));
    }
}

__device__ __forceinline__ uint32_t smem_u32_of(const void* p) {
    uint32_t a;
    asm("{ .reg .u64 t; cvta.to.shared.u64 t, %1; cvt.u32.u64 %0, t; }" : "=r"(a) : "l"(p));
    return a;
}

#define LDMATRIX_X4(r0, r1, r2, r3, addr)                                    \
    asm volatile("ldmatrix.sync.aligned.m8n8.x4.shared.b16 {%0,%1,%2,%3}, [%4];" \
                 : "=r"(r0), "=r"(r1), "=r"(r2), "=r"(r3) : "r"(addr))

#define MMA16816(d, a, b0, b1)                                               \
    asm volatile("mma.sync.aligned.m16n8k16.row.col.f32.bf16.bf16.f32 "      \
                 "{%0,%1,%2,%3},{%4,%5,%6,%7},{%8,%9},{%0,%1,%2,%3};"        \
                 : "+f"((d)[0]), "+f"((d)[1]), "+f"((d)[2]), "+f"((d)[3])    \
                 : "r"((a)[0]), "r"((a)[1]), "r"((a)[2]), "r"((a)[3]),       \
                   "r"(b0), "r"(b1))

#define CP_ASYNC16(dst, src) \
    asm volatile("cp.async.cg.shared.global [%0], [%1], 16;" :: "r"(dst), "l"(src))

// smem: A stages [0, 16KB) (2 x 8KB), B stages [16KB, 80KB) (2 x 32KB).
// Row = 128B = [hi 64B | lo 64B] of 32 k-elems, SWZ-swizzled. A: 64 rows, B: 256 rows.
#define A_STAGE  8192
#define B_STAGE  32768
#define B_BASE   16384
#define SMEM_TOTAL 81920

__global__ __launch_bounds__(256, 2)
void conv_mma_kernel(const float* __restrict__ x,
                     const float* __restrict__ bias,
                     float* __restrict__ out)
{
    extern __shared__ char smem[];
    const uint32_t smem_u = smem_u32_of(smem);

    const int tid = threadIdx.x;
    const int lid = tid & 31;
    const int wid = tid >> 5;
    const int mb  = blockIdx.x;          // 0..255
    const int n   = mb >> 4;             // image
    const int oip = mb & 15;             // output-row pair: oi_g in {2*oip, 2*oip+1}

    // ---- A gather geometry: warp = 32 consecutive oj lanes ----
    const int oj_g   = tid & 31;
    const int g      = tid >> 5;         // warp id
    const int oi_loc = g & 1;
    const int ks     = (g >> 1) * 8;     // k-subrange [ks, ks+8)
    const int arow   = oi_loc * 32 + oj_g;
    const int yb     = 2 * (2 * oip + oi_loc) - 1;   // y for kh=0
    const int xb0    = 2 * oj_g - 1;                 // x for kw=0
    const float* xbp = x + (size_t)n * CIN * HW * HW;

    // ---- B cp.async mapping: 8 x 16B per thread per chunk ----
    // q = i*256 + tid: brow = i*32 + (tid>>3), unit = tid&7 (same for all i)
    const int trow = tid >> 3;
    const int unit = tid & 7;
    const int term = unit >> 2;          // 0=hi,1=lo
    const int k16  = unit & 3;
    const __nv_bfloat16* bsrc0 = (term ? g_wlo : g_whi) + (size_t)trow * KTOT + k16 * 8;
    const uint32_t bdst0 = SWZ((uint32_t)(trow * 128 + unit * 16));
    // per i: src += 32*KTOT elems, dst += 4096 bytes (swizzle-invariant: 32 rows)

    float acc[2][8][4];
#pragma unroll
    for (int a = 0; a < 2; a++)
#pragma unroll
        for (int b = 0; b < 8; b++)
#pragma unroll
            for (int c = 0; c < 4; c++) acc[a][b][c] = 0.0f;

    float v[8];

    auto gatherA = [&](int c) {
#pragma unroll
        for (int j = 0; j < 8; j++) {
            const int k   = c * 32 + ks + j;
            const int cin = (k * 7282) >> 16;       // k/9 for k<2304
            const int tap = k - cin * 9;
            const int kh  = (tap * 11) >> 5;        // tap/3
            const int kw  = tap - kh * 3;
            const int y   = yb + kh;                // [-1, 63]
            const int xx  = xb0 + kw;               // [-1, 63]
            const bool ok = (y >= 0) & (xx >= 0);
            v[j] = ok ? __ldg(xbp + (cin << 12) + (y << 6) + xx) : 0.0f;
        }
    };

    auto stsA = [&](int c) {
        char* abuf = smem + (c & 1) * A_STAGE;
        uint32_t hp[4], lp[4];
#pragma unroll
        for (int j = 0; j < 4; j++) {
            __nv_bfloat16 h0 = __float2bfloat16(v[2 * j]);
            __nv_bfloat16 h1 = __float2bfloat16(v[2 * j + 1]);
            __nv_bfloat16 l0 = __float2bfloat16(v[2 * j]     - __bfloat162float(h0));
            __nv_bfloat16 l1 = __float2bfloat16(v[2 * j + 1] - __bfloat162float(h1));
            hp[j] = (uint32_t)__bfloat16_as_ushort(h0) |
                    ((uint32_t)__bfloat16_as_ushort(h1) << 16);
            lp[j] = (uint32_t)__bfloat16_as_ushort(l0) |
                    ((uint32_t)__bfloat16_as_ushort(l1) << 16);
        }
        const uint32_t base = (uint32_t)(arow * 128 + ks * 2);
        *(uint4*)(abuf + SWZ(base))      = make_uint4(hp[0], hp[1], hp[2], hp[3]);
        *(uint4*)(abuf + SWZ(base + 64)) = make_uint4(lp[0], lp[1], lp[2], lp[3]);
    };

    auto issueB = [&](int c) {
        const uint32_t bb = smem_u + B_BASE + (c & 1) * B_STAGE;
        const __nv_bfloat16* src = bsrc0 + c * 32;
#pragma unroll
        for (int i = 0; i < 8; i++)
            CP_ASYNC16(bb + bdst0 + i * 4096, (const void*)(src + i * 32 * KTOT));
        asm volatile("cp.async.commit_group;");
    };

    const int wm = wid >> 2;   // 0..1  (oi_loc of consumer tile)
    const int wn = wid & 3;    // 0..3  (64-cout slice)

    // ---- prologue ----
    gatherA(0);
    issueB(0);

    for (int c = 0; c < NCHUNK; ++c) {
        stsA(c);
        if (c < NCHUNK - 1) gatherA(c + 1);
        asm volatile("cp.async.wait_group 0;");
        __syncthreads();
        if (c < NCHUNK - 1) issueB(c + 1);

        const uint32_t ab = smem_u + (c & 1) * A_STAGE;
        const uint32_t bb = smem_u + B_BASE + (c & 1) * B_STAGE;

#pragma unroll
        for (int kb = 0; kb < 2; kb++) {
            uint32_t AH[2][4], AL[2][4];
#pragma unroll
            for (int mt = 0; mt < 2; mt++) {
                const int mrow = wm * 32 + mt * 16 + ((lid >> 3) & 1) * 8 + (lid & 7);
                const int kby  = kb * 32 + (lid >> 4) * 16;
                LDMATRIX_X4(AH[mt][0], AH[mt][1], AH[mt][2], AH[mt][3],
                            ab + SWZ((uint32_t)(mrow * 128 + kby)));
                LDMATRIX_X4(AL[mt][0], AL[mt][1], AL[mt][2], AL[mt][3],
                            ab + SWZ((uint32_t)(mrow * 128 + 64 + kby)));
            }
#pragma unroll
            for (int ntile = 0; ntile < 4; ntile++) {
                uint32_t BH[4], BL[4];
                const int nrow = wn * 64 + ntile * 16 + (lid >> 4) * 8 + (lid & 7);
                const int kbyB = kb * 32 + ((lid >> 3) & 1) * 16;
                LDMATRIX_X4(BH[0], BH[1], BH[2], BH[3],
                            bb + SWZ((uint32_t)(nrow * 128 + kbyB)));
                LDMATRIX_X4(BL[0], BL[1], BL[2], BL[3],
                            bb + SWZ((uint32_t)(nrow * 128 + 64 + kbyB)));
#pragma unroll
                for (int mt = 0; mt < 2; mt++) {
#pragma unroll
                    for (int nh = 0; nh < 2; nh++) {
                        const int sb = nh * 2;
                        float* d = acc[mt][ntile * 2 + nh];
                        MMA16816(d, AH[mt], BH[sb], BH[sb + 1]);
                        MMA16816(d, AH[mt], BL[sb], BL[sb + 1]);
                        MMA16816(d, AL[mt], BH[sb], BH[sb + 1]);
                    }
                }
            }
        }
    }

    // ---- epilogue: bias + permuted store ----
    // m-row r = wm*32 + mt*16 + (lid>>2) (+8): oi_g = 2*oip + wm, oj = r & 31.
    // p = (si*2 + sj)*256 + i*16 + j with si = oi_g&1 = wm, i = oip, sj = oj&1, j = oj>>1.
#pragma unroll
    for (int mt = 0; mt < 2; mt++) {
#pragma unroll
        for (int nt = 0; nt < 8; nt++) {
            const int oj = mt * 16 + (lid >> 2);
            const int sj = oj & 1;
            const int p0 = ((wm * 2 + sj) << 8) + (oip << 4) + (oj >> 1);
            const int p1 = p0 + 4;                      // oj+8 -> j+4, same sj
            const int c0 = wn * 64 + nt * 8 + (lid & 3) * 2;
            const float2 bv = *(const float2*)&bias[c0];
            float* o0 = out + ((size_t)(n * COUT + c0)) * PP;
            float* o1 = o0 + PP;
            o0[p0] = acc[mt][nt][0] + bv.x;
            o1[p0] = acc[mt][nt][1] + bv.y;
            o0[p1] = acc[mt][nt][2] + bv.x;
            o1[p1] = acc[mt][nt][3] + bv.y;
        }
    }
}

extern "C" void kernel_launch(void* const* d_in, const int* in_sizes, int n_in,
                              void* d_out, int out_size)
{
    (void)in_sizes; (void)n_in; (void)out_size;
    const float* x    = (const float*)d_in[0];
    const float* wgt  = (const float*)d_in[1];
    const float* bias = (const float*)d_in[2];
    float* out        = (float*)d_out;

    wconv_kernel<<<(COUT * KTOT + 511) / 512, 512>>>(wgt);

    cudaFuncSetAttribute(conv_mma_kernel,
                         cudaFuncAttributeMaxDynamicSharedMemorySize, SMEM_TOTAL);
    conv_mma_kernel<<<256, 256, SMEM_TOTAL>>>(x, bias, out);
}

// round 8
// speedup vs baseline: 5.1668x; 1.3594x over previous
#include <cuda_runtime.h>
#include <cuda_fp16.h>
#include <cstdint>

// Conv2d 3x3 s2 p1 as implicit GEMM with mma.sync, fp16 2-term K-packed split.
// v = h + l (fp16 each); A slots = [ah, al], B slots = [bh, bh] ->
// one mma accumulates ah*bh + al*bh = a*bh; dropped a*bl ~ 2^-11 rel (< 1e-3).
// x[16,256,64,64] fp32, w[256,256,3,3] fp32, bias[256] -> out fp32, permuted.
// M = 16384, N = 256, K = 2304 = 72 chunks of 32 (64 packed slots).

#define CIN    256
#define COUT   256
#define HW     64
#define PP     1024
#define KTOT   2304
#define NCHUNK 72

#define SWZ(o) ((o) ^ (((o) >> 3) & 0x70))

// preconverted weights: word k = (bh | bh<<16), K-major [cout][k]
__device__ __align__(16) uint32_t g_wext[COUT * KTOT];

__global__ void wconv_kernel(const float* __restrict__ w) {
    int i = blockIdx.x * blockDim.x + threadIdx.x;
    if (i < COUT * KTOT) {
        const uint32_t h = (uint32_t)__half_as_ushort(__float2half_rn(w[i]));
        g_wext[i] = h | (h << 16);
    }
}

__device__ __forceinline__ uint32_t smem_u32_of(const void* p) {
    uint32_t a;
    asm("{ .reg .u64 t; cvta.to.shared.u64 t, %1; cvt.u32.u64 %0, t; }" : "=r"(a) : "l"(p));
    return a;
}

#define LDMATRIX_X4(r0, r1, r2, r3, addr)                                    \
    asm volatile("ldmatrix.sync.aligned.m8n8.x4.shared.b16 {%0,%1,%2,%3}, [%4];" \
                 : "=r"(r0), "=r"(r1), "=r"(r2), "=r"(r3) : "r"(addr))

#define MMA16816F16(d, a, b0, b1)                                            \
    asm volatile("mma.sync.aligned.m16n8k16.row.col.f32.f16.f16.f32 "        \
                 "{%0,%1,%2,%3},{%4,%5,%6,%7},{%8,%9},{%0,%1,%2,%3};"        \
                 : "+f"((d)[0]), "+f"((d)[1]), "+f"((d)[2]), "+f"((d)[3])    \
                 : "r"((a)[0]), "r"((a)[1]), "r"((a)[2]), "r"((a)[3]),       \
                   "r"(b0), "r"(b1))

#define CP_ASYNC16(dst, src) \
    asm volatile("cp.async.cg.shared.global [%0], [%1], 16;" :: "r"(dst), "l"(src))

// smem: A stages [0, 16KB) (2 x 8KB), B stages [16KB, 80KB) (2 x 32KB).
// Row = 128B = 64 fp16 k-slots (32 original k), SWZ-swizzled. A: 64 rows, B: 256.
#define A_STAGE  8192
#define B_STAGE  32768
#define B_BASE   16384
#define SMEM_TOTAL 81920

__global__ __launch_bounds__(256, 2)
void conv_mma_kernel(const float* __restrict__ x,
                     const float* __restrict__ bias,
                     float* __restrict__ out)
{
    extern __shared__ char smem[];
    const uint32_t smem_u = smem_u32_of(smem);

    const int tid = threadIdx.x;
    const int lid = tid & 31;
    const int wid = tid >> 5;
    const int mb  = blockIdx.x;          // 0..255
    const int n   = mb >> 4;             // image
    const int oip = mb & 15;             // output-row pair: oi_g in {2*oip, 2*oip+1}

    // ---- A gather geometry: warp = 32 consecutive oj lanes ----
    const int oj_g   = tid & 31;
    const int g      = tid >> 5;         // warp id
    const int oi_loc = g & 1;
    const int ks     = (g >> 1) * 8;     // original-k subrange [ks, ks+8)
    const int arow   = oi_loc * 32 + oj_g;
    const int yb     = 2 * (2 * oip + oi_loc) - 1;   // y for kh=0
    const int xb0    = 2 * oj_g - 1;                 // x for kw=0
    const float* xbp = x + (size_t)n * CIN * HW * HW;

    // ---- B cp.async mapping: 8 x 16B per thread per chunk ----
    const int trow = tid >> 3;          // row within 32-row group
    const int u16  = tid & 7;           // 16B unit in row
    const uint32_t* bsrc0 = g_wext + (size_t)trow * KTOT + u16 * 4;
    const uint32_t bdst0  = SWZ((uint32_t)(trow * 128 + u16 * 16));
    // per i (0..7): src += 32*KTOT words, dst += 4096 bytes (swizzle-invariant)

    float acc[2][8][4];
#pragma unroll
    for (int a = 0; a < 2; a++)
#pragma unroll
        for (int b = 0; b < 8; b++)
#pragma unroll
            for (int c = 0; c < 4; c++) acc[a][b][c] = 0.0f;

    float v[8];

    auto gatherA = [&](int c) {
#pragma unroll
        for (int j = 0; j < 8; j++) {
            const int k   = c * 32 + ks + j;
            const int cin = (k * 7282) >> 16;       // k/9 for k<2304
            const int tap = k - cin * 9;
            const int kh  = (tap * 11) >> 5;        // tap/3
            const int kw  = tap - kh * 3;
            const int y   = yb + kh;                // [-1, 63]
            const int xx  = xb0 + kw;               // [-1, 63]
            const bool ok = (y >= 0) & (xx >= 0);
            v[j] = ok ? __ldg(xbp + (cin << 12) + (y << 6) + xx) : 0.0f;
        }
    };

    auto stsA = [&](int c) {
        char* abuf = smem + (c & 1) * A_STAGE;
        uint32_t w[8];
#pragma unroll
        for (int j = 0; j < 8; j++) {
            const __half h = __float2half_rn(v[j]);
            const __half l = __float2half_rn(v[j] - __half2float(h));
            w[j] = (uint32_t)__half_as_ushort(h) |
                   ((uint32_t)__half_as_ushort(l) << 16);   // slots (2k, 2k+1)
        }
        const uint32_t base = (uint32_t)(arow * 128 + ks * 4);
        *(uint4*)(abuf + SWZ(base))      = make_uint4(w[0], w[1], w[2], w[3]);
        *(uint4*)(abuf + SWZ(base + 16)) = make_uint4(w[4], w[5], w[6], w[7]);
    };

    auto issueB = [&](int c) {
        const uint32_t bb = smem_u + B_BASE + (c & 1) * B_STAGE;
        const uint32_t* src = bsrc0 + c * 32;
#pragma unroll
        for (int i = 0; i < 8; i++)
            CP_ASYNC16(bb + bdst0 + i * 4096, (const void*)(src + i * 32 * KTOT));
        asm volatile("cp.async.commit_group;");
    };

    const int wm = wid >> 2;   // 0..1  (oi_loc of consumer tile)
    const int wn = wid & 3;    // 0..3  (64-cout slice)

    // ---- prologue ----
    gatherA(0);
    issueB(0);

    for (int c = 0; c < NCHUNK; ++c) {
        stsA(c);
        if (c < NCHUNK - 1) gatherA(c + 1);
        asm volatile("cp.async.wait_group 0;");
        __syncthreads();
        if (c < NCHUNK - 1) issueB(c + 1);

        const uint32_t ab = smem_u + (c & 1) * A_STAGE;
        const uint32_t bb = smem_u + B_BASE + (c & 1) * B_STAGE;

#pragma unroll
        for (int kb = 0; kb < 4; kb++) {          // 4 x 16 slots = 64 slots
            uint32_t A0[2][4];
#pragma unroll
            for (int mt = 0; mt < 2; mt++) {
                const int mrow = wm * 32 + mt * 16 + ((lid >> 3) & 1) * 8 + (lid & 7);
                const int kby  = kb * 32 + (lid >> 4) * 16;
                LDMATRIX_X4(A0[mt][0], A0[mt][1], A0[mt][2], A0[mt][3],
                            ab + SWZ((uint32_t)(mrow * 128 + kby)));
            }
#pragma unroll
            for (int ntile = 0; ntile < 4; ntile++) {
                uint32_t B0[4];
                const int nrow = wn * 64 + ntile * 16 + (lid >> 4) * 8 + (lid & 7);
                const int kbyB = kb * 32 + ((lid >> 3) & 1) * 16;
                LDMATRIX_X4(B0[0], B0[1], B0[2], B0[3],
                            bb + SWZ((uint32_t)(nrow * 128 + kbyB)));
#pragma unroll
                for (int mt = 0; mt < 2; mt++) {
#pragma unroll
                    for (int nh = 0; nh < 2; nh++) {
                        const int sb = nh * 2;
                        MMA16816F16(acc[mt][ntile * 2 + nh], A0[mt],
                                    B0[sb], B0[sb + 1]);
                    }
                }
            }
        }
    }

    // ---- epilogue: bias + permuted store ----
    // m-row r = wm*32 + mt*16 + (lid>>2) (+8): oi_g = 2*oip + wm, oj = r & 31.
    // p = (si*2 + sj)*256 + i*16 + j with si = wm, i = oip, sj = oj&1, j = oj>>1.
#pragma unroll
    for (int mt = 0; mt < 2; mt++) {
#pragma unroll
        for (int nt = 0; nt < 8; nt++) {
            const int oj = mt * 16 + (lid >> 2);
            const int sj = oj & 1;
            const int p0 = ((wm * 2 + sj) << 8) + (oip << 4) + (oj >> 1);
            const int p1 = p0 + 4;                      // oj+8 -> j+4, same sj
            const int c0 = wn * 64 + nt * 8 + (lid & 3) * 2;
            const float2 bv = *(const float2*)&bias[c0];
            float* o0 = out + ((size_t)(n * COUT + c0)) * PP;
            float* o1 = o0 + PP;
            o0[p0] = acc[mt][nt][0] + bv.x;
            o1[p0] = acc[mt][nt][1] + bv.y;
            o0[p1] = acc[mt][nt][2] + bv.x;
            o1[p1] = acc[mt][nt][3] + bv.y;
        }
    }
}

extern "C" void kernel_launch(void* const* d_in, const int* in_sizes, int n_in,
                              void* d_out, int out_size)
{
    (void)in_sizes; (void)n_in; (void)out_size;
    const float* x    = (const float*)d_in[0];
    const float* wgt  = (const float*)d_in[1];
    const float* bias = (const float*)d_in[2];
    float* out        = (float*)d_out;

    wconv_kernel<<<(COUT * KTOT + 511) / 512, 512>>>(wgt);

    cudaFuncSetAttribute(conv_mma_kernel,
                         cudaFuncAttributeMaxDynamicSharedMemorySize, SMEM_TOTAL);
    conv_mma_kernel<<<256, 256, SMEM_TOTAL>>>(x, bias, out);
}